// round 4
// baseline (speedup 1.0000x reference)
#include <cuda_runtime.h>
#include <cstdint>

// Problem constants (fixed by the dataset)
#define BATCH   16
#define C_IN    64
#define HH      32
#define WW      32
#define C_OUT   128
#define PH      34          // padded plane height (1 + 32 + 1)
#define PW      40          // padded plane width: 4 left + 32 + 4 right (16B-aligned interior)
#define PLANE   (PH*PW)     // 1360 floats
#define BUF     (2*PLANE)   // one batch = 2 planes = 2720 floats
#define NB      2           // batches per block

// 16B async copy global->shared (LDGSTS)
__device__ __forceinline__ void cp16(float* dst_smem, const float* src) {
    uint32_t d = (uint32_t)__cvta_generic_to_shared(dst_smem);
    asm volatile("cp.async.cg.shared.global [%0], [%1], 16;\n" :: "r"(d), "l"(src));
}

// gate(a,b) = c0 + ca*a + cb*b + cab*a*b, factored to 3 FMAs:
//   fma(fma(cab,b,ca), a, fma(cb,b,c0))
__device__ __forceinline__ float gate3(const float k[4], float a, float b) {
    return fmaf(fmaf(k[3], b, k[1]), a, fmaf(k[2], b, k[0]));
}

// ---------------------------------------------------------------------------
// One block per (oc, batch-pair). Stages 2 batches x 2 channel planes via
// cp.async (double-buffered: compute batch 0 while batch 1 is in flight),
// softmax coefficients computed once per block by threads 0..3, hot loop is
// 8 LDS + 21 FMA + 1 STG per pixel with immediate-offset addressing.
// ---------------------------------------------------------------------------
__global__ void __launch_bounds__(256)
tree_kernel(const float* __restrict__ x,
            const float* __restrict__ w,
            const int*   __restrict__ leaf_idx,
            float*       __restrict__ out)
{
    __shared__ __align__(16) float sm[NB * BUF];   // 21760 B
    __shared__ float s_coef[16];                   // 4 gates x {c0,ca,cb,cab}

    const int blk = blockIdx.x;          // 0..1023
    const int oc  = blk & (C_OUT - 1);
    const int bg  = blk >> 7;            // 0..7 -> batches 2*bg, 2*bg+1
    const int tid = threadIdx.x;

    // --- leaf offsets + source channels (broadcast loads, no smem/sync) ---
    int off[8];
    int chA = 0, chB = 0;
    #pragma unroll
    for (int i = 0; i < 8; i++) {
        int idx = __ldg(&leaf_idx[oc * 8 + i]);
        int ch  = idx / 9;
        int pos = idx - ch * 9;
        int ki  = pos / 3;
        int kj  = pos - ki * 3;
        off[i]  = (i >> 2) * PLANE + ki * PW + kj;
        if (i == 0) chA = ch;
        if (i == 4) chB = ch;
    }

    // --- issue async stages for both batches (one commit group per batch) --
    // Per batch: 2 planes x 32 rows x 8 float4 = 512 copies -> 2 per thread.
    #pragma unroll
    for (int u = 0; u < NB; u++) {
        const float* xb = x + ((size_t)(bg * NB + u) * C_IN) * (HH * WW);
        #pragma unroll
        for (int i = 0; i < 2; i++) {
            int t  = tid + i * 256;      // 0..511
            int p  = t >> 8;             // plane select
            int j  = t & 255;            // r*8 + c4
            int r  = j >> 3;
            int c4 = j & 7;
            const float* src = xb + (p ? chB : chA) * (HH * WW) + j * 4;
            float* dst = sm + u * BUF + p * PLANE + (r + 1) * PW + 4 + c4 * 4;
            cp16(dst, src);
        }
        asm volatile("cp.async.commit_group;\n");
    }

    // --- zero the borders actually read by the gather -----------------
    // Per plane (84 float4): rows 0..33 col-groups {0, 9} (cols 0-3, 36-39),
    // plus rows 0 and 33 col-groups 1..8 (cols 4-35). 4 planes -> 336.
    {
        float4 z = make_float4(0.f, 0.f, 0.f, 0.f);
        float4* smv = (float4*)sm;
        #pragma unroll
        for (int i = 0; i < 2; i++) {
            int t = tid + i * 256;
            if (t < 336) {
                int q = t / 84;              // plane 0..3 (contiguous)
                int k = t - q * 84;
                int f4;
                if (k < 68) {
                    f4 = (k >> 1) * 10 + ((k & 1) ? 9 : 0);
                } else {
                    int row = (k < 76) ? 0 : 33;
                    int c   = k - ((k < 76) ? 68 : 76) + 1;
                    f4 = row * 10 + c;
                }
                smv[q * (PLANE / 4) + f4] = z;
            }
        }
    }

    // --- softmax -> 4 affine coefficients, threads 0..3 (gate = tid) -----
    // op order: 0, ab, a-ab, a, b-ab, b, s-2ab, s-ab, 1-(s-ab), 1-(s-2ab),
    //           1-b, 1-b+ab, 1-a, 1-a+ab, 1-ab, 1
    if (tid < 4) {
        const float T0[16]  = {0,0,0,0,0,0,0,0, 1, 1, 1, 1, 1, 1, 1, 1};
        const float TA[16]  = {0,0,1,1,0,0,1,1,-1,-1, 0, 0,-1,-1, 0, 0};
        const float TB[16]  = {0,0,0,0,1,1,1,1,-1,-1,-1,-1, 0, 0, 0, 0};
        const float TAB[16] = {0,1,-1,0,-1,0,-2,-1, 1, 2, 0, 1, 0, 1,-1, 0};

        const float* wp = w + (oc * 7 + tid) * 16;   // weights [C_out, 7, 16]

        float m = wp[0];
        #pragma unroll
        for (int i = 1; i < 16; i++) m = fmaxf(m, wp[i]);

        float e[16];
        float s = 0.f;
        #pragma unroll
        for (int i = 0; i < 16; i++) { e[i] = __expf(wp[i] - m); s += e[i]; }
        float inv = 1.f / s;

        float c0 = 0.f, ca = 0.f, cb = 0.f, cab = 0.f;
        #pragma unroll
        for (int i = 0; i < 16; i++) {
            c0  += e[i] * T0[i];
            ca  += e[i] * TA[i];
            cb  += e[i] * TB[i];
            cab += e[i] * TAB[i];
        }
        s_coef[tid * 4 + 0] = c0 * inv;
        s_coef[tid * 4 + 1] = ca * inv;
        s_coef[tid * 4 + 2] = cb * inv;
        s_coef[tid * 4 + 3] = cab * inv;
    }

    // --- batch 0 ready (1 group still pending) + borders/coefs visible ---
    asm volatile("cp.async.wait_group 1;\n");
    __syncthreads();

    // Coefficients to registers
    float k0[4], k1[4], k2[4], k3[4];
    #pragma unroll
    for (int i = 0; i < 4; i++) { k0[i] = s_coef[i];      k1[i] = s_coef[4+i];
                                  k2[i] = s_coef[8+i];    k3[i] = s_coef[12+i]; }

    // Per-thread base pixel: y = tid>>5, x = tid&31 -> padded col x+3
    const int pb0 = (tid >> 5) * PW + (tid & 31) + 3;

    #pragma unroll
    for (int u = 0; u < NB; u++) {
        if (u == 1) {
            asm volatile("cp.async.wait_group 0;\n");
            __syncthreads();
        }
        const float* bp = sm + u * BUF + pb0;
        float* ob = out + ((size_t)(bg * NB + u) * C_OUT + oc) * (HH * WW) + tid;

        #pragma unroll
        for (int t = 0; t < 4; t++) {
            const int d = t * 8 * PW;        // +8 rows per step (256 pixels)

            float l0 = bp[off[0] + d], l1 = bp[off[1] + d];
            float l2 = bp[off[2] + d], l3 = bp[off[3] + d];
            float l4 = bp[off[4] + d], l5 = bp[off[5] + d];
            float l6 = bp[off[6] + d], l7 = bp[off[7] + d];

            // level 0: weight rows 0,1,2,3
            float m0 = gate3(k0, l0, l1);
            float m1 = gate3(k1, l2, l3);
            float m2 = gate3(k2, l4, l5);
            float m3 = gate3(k3, l6, l7);
            // level 1: rows 1,2
            float n0 = gate3(k1, m0, m1);
            float n1 = gate3(k2, m2, m3);
            // level 2: row 3
            float r  = gate3(k3, n0, n1);

            ob[t * 256] = r;
        }
    }
}

extern "C" void kernel_launch(void* const* d_in, const int* in_sizes, int n_in,
                              void* d_out, int out_size)
{
    const float* x   = (const float*)d_in[0];          // [16,64,32,32]
    const float* w   = (const float*)d_in[1];          // [128,7,16]
    const int*   idx = (const int*)d_in[2];            // [128,8]
    float*       out = (float*)d_out;                  // [16,128,32,32]

    tree_kernel<<<(BATCH / NB) * C_OUT, 256>>>(x, w, idx, out);
}

// round 5
// speedup vs baseline: 1.0238x; 1.0238x over previous
#include <cuda_runtime.h>
#include <cstdint>

// Problem constants (fixed by the dataset)
#define BATCH   16
#define C_IN    64
#define HH      32
#define WW      32
#define C_OUT   128
#define PH      34          // padded plane height (1 + 32 + 1)
#define PW      40          // padded plane width: 4 left + 32 + 4 right (16B-aligned interior)
#define PLANE   (PH*PW)     // 1360 floats
#define PLANE4  (PLANE/4)   // 340 float4
#define BUF     (2*PLANE)   // one batch = 2 planes = 2720 floats
#define NB      2           // batches per block

// 16B async copy global->shared (LDGSTS)
__device__ __forceinline__ void cp16(float* dst_smem, const float* src) {
    uint32_t d = (uint32_t)__cvta_generic_to_shared(dst_smem);
    asm volatile("cp.async.cg.shared.global [%0], [%1], 16;\n" :: "r"(d), "l"(src));
}

// gate(a,b) = c0 + ca*a + cb*b + cab*a*b, factored to 3 FMAs:
//   fma(fma(cab,b,ca), a, fma(cb,b,c0))
__device__ __forceinline__ float gate3(const float k[4], float a, float b) {
    return fmaf(fmaf(k[3], b, k[1]), a, fmaf(k[2], b, k[0]));
}

// ---------------------------------------------------------------------------
// One block per (oc, batch-pair). Stages 2 batches x 2 channel planes via
// cp.async (double-buffered), softmax coefficients by threads 0..3, leaf
// offsets decoded once by threads 0..7 into smem. Hot loop: 8 LDS + 21 FMA
// + 1 STG per pixel, immediate-offset addressing, no integer divisions
// anywhere on the all-threads path except 2 const divs (mul-hi).
// ---------------------------------------------------------------------------
__global__ void __launch_bounds__(256)
tree_kernel(const float* __restrict__ x,
            const float* __restrict__ w,
            const int*   __restrict__ leaf_idx,
            float*       __restrict__ out)
{
    __shared__ __align__(16) float sm[NB * BUF];   // 21760 B
    __shared__ float s_coef[16];                   // 4 gates x {c0,ca,cb,cab}
    __shared__ int   s_off[8];                     // leaf smem offsets

    const int blk = blockIdx.x;          // 0..1023
    const int oc  = blk & (C_OUT - 1);
    const int bg  = blk >> 7;            // 0..7 -> batches 2*bg, 2*bg+1
    const int tid = threadIdx.x;

    // --- source channels (broadcast loads; const-div -> mul-hi) ----------
    const int chA = __ldg(&leaf_idx[oc * 8 + 0]) / 9;
    const int chB = __ldg(&leaf_idx[oc * 8 + 4]) / 9;

    // --- issue async stages for both batches (one commit group per batch) --
    // Per batch: 2 planes x 32 rows x 8 float4 = 512 copies -> 2 per thread.
    #pragma unroll
    for (int u = 0; u < NB; u++) {
        const float* xb = x + ((size_t)(bg * NB + u) * C_IN) * (HH * WW);
        #pragma unroll
        for (int i = 0; i < 2; i++) {
            int t  = tid + i * 256;      // 0..511
            int p  = t >> 8;             // plane select
            int j  = t & 255;            // r*8 + c4
            int r  = j >> 3;
            int c4 = j & 7;
            const float* src = xb + (p ? chB : chA) * (HH * WW) + j * 4;
            float* dst = sm + u * BUF + p * PLANE + (r + 1) * PW + 4 + c4 * 4;
            cp16(dst, src);
        }
        asm volatile("cp.async.commit_group;\n");
    }

    // --- zero the borders actually read by the gather (no divisions) -----
    // Per plane, 84 float4 slots padded to 128: slots k<68 are side col-groups
    // {0,9} of rows 0..33; 68..75 row 0 cols 4..35; 76..83 row 33 cols 4..35.
    {
        float4 z = make_float4(0.f, 0.f, 0.f, 0.f);
        float4* smv = (float4*)sm;
        #pragma unroll
        for (int i = 0; i < 2; i++) {
            int t = tid + i * 256;       // 0..511 = 4 planes x 128 slots
            int q = t >> 7;              // plane 0..3 (contiguous buffers)
            int k = t & 127;
            if (k < 84) {
                int f4;
                if (k < 68)      f4 = (k >> 1) * 10 + ((k & 1) ? 9 : 0);
                else if (k < 76) f4 = k - 67;            // row 0, groups 1..8
                else             f4 = 330 + (k - 75);    // row 33, groups 1..8
                smv[q * PLANE4 + f4] = z;
            }
        }
    }

    // --- leaf offsets: threads 0..7 decode into smem ----------------------
    if (tid < 8) {
        int idx = __ldg(&leaf_idx[oc * 8 + tid]);
        int ch  = idx / 9;
        int pos = idx - ch * 9;
        int ki  = pos / 3;
        int kj  = pos - ki * 3;
        s_off[tid] = (tid >> 2) * PLANE + ki * PW + kj;
    }

    // --- softmax -> 4 affine coefficients, threads 0..3 (gate = tid) -----
    // op order: 0, ab, a-ab, a, b-ab, b, s-2ab, s-ab, 1-(s-ab), 1-(s-2ab),
    //           1-b, 1-b+ab, 1-a, 1-a+ab, 1-ab, 1
    if (tid < 4) {
        const float T0[16]  = {0,0,0,0,0,0,0,0, 1, 1, 1, 1, 1, 1, 1, 1};
        const float TA[16]  = {0,0,1,1,0,0,1,1,-1,-1, 0, 0,-1,-1, 0, 0};
        const float TB[16]  = {0,0,0,0,1,1,1,1,-1,-1,-1,-1, 0, 0, 0, 0};
        const float TAB[16] = {0,1,-1,0,-1,0,-2,-1, 1, 2, 0, 1, 0, 1,-1, 0};

        const float* wp = w + (oc * 7 + tid) * 16;   // weights [C_out, 7, 16]

        float m = wp[0];
        #pragma unroll
        for (int i = 1; i < 16; i++) m = fmaxf(m, wp[i]);

        float e[16];
        float s = 0.f;
        #pragma unroll
        for (int i = 0; i < 16; i++) { e[i] = __expf(wp[i] - m); s += e[i]; }
        float inv = 1.f / s;

        float c0 = 0.f, ca = 0.f, cb = 0.f, cab = 0.f;
        #pragma unroll
        for (int i = 0; i < 16; i++) {
            c0  += e[i] * T0[i];
            ca  += e[i] * TA[i];
            cb  += e[i] * TB[i];
            cab += e[i] * TAB[i];
        }
        s_coef[tid * 4 + 0] = c0 * inv;
        s_coef[tid * 4 + 1] = ca * inv;
        s_coef[tid * 4 + 2] = cb * inv;
        s_coef[tid * 4 + 3] = cab * inv;
    }

    // --- batch 0 ready (1 group still pending) + smem metadata visible ---
    asm volatile("cp.async.wait_group 1;\n");
    __syncthreads();

    // Coefficients + leaf offsets to registers (broadcast LDS)
    float k0[4], k1[4], k2[4], k3[4];
    #pragma unroll
    for (int i = 0; i < 4; i++) { k0[i] = s_coef[i];      k1[i] = s_coef[4+i];
                                  k2[i] = s_coef[8+i];    k3[i] = s_coef[12+i]; }

    // Per-thread base pixel: y = tid>>5, x = tid&31 -> padded col x+3
    const int pb0 = (tid >> 5) * PW + (tid & 31) + 3;
    const int o0 = s_off[0] + pb0, o1 = s_off[1] + pb0;
    const int o2 = s_off[2] + pb0, o3 = s_off[3] + pb0;
    const int o4 = s_off[4] + pb0, o5 = s_off[5] + pb0;
    const int o6 = s_off[6] + pb0, o7 = s_off[7] + pb0;

    #pragma unroll
    for (int u = 0; u < NB; u++) {
        if (u == 1) {
            asm volatile("cp.async.wait_group 0;\n");
            __syncthreads();
        }
        const float* bp = sm + u * BUF;
        float* ob = out + ((size_t)(bg * NB + u) * C_OUT + oc) * (HH * WW) + tid;

        #pragma unroll
        for (int t = 0; t < 4; t++) {
            const int d = t * 8 * PW;        // +8 rows per step (256 pixels)

            float l0 = bp[o0 + d], l1 = bp[o1 + d];
            float l2 = bp[o2 + d], l3 = bp[o3 + d];
            float l4 = bp[o4 + d], l5 = bp[o5 + d];
            float l6 = bp[o6 + d], l7 = bp[o7 + d];

            // level 0: weight rows 0,1,2,3
            float m0 = gate3(k0, l0, l1);
            float m1 = gate3(k1, l2, l3);
            float m2 = gate3(k2, l4, l5);
            float m3 = gate3(k3, l6, l7);
            // level 1: rows 1,2
            float n0 = gate3(k1, m0, m1);
            float n1 = gate3(k2, m2, m3);
            // level 2: row 3
            float r  = gate3(k3, n0, n1);

            ob[t * 256] = r;
        }
    }
}

extern "C" void kernel_launch(void* const* d_in, const int* in_sizes, int n_in,
                              void* d_out, int out_size)
{
    const float* x   = (const float*)d_in[0];          // [16,64,32,32]
    const float* w   = (const float*)d_in[1];          // [128,7,16]
    const int*   idx = (const int*)d_in[2];            // [128,8]
    float*       out = (float*)d_out;                  // [16,128,32,32]

    tree_kernel<<<(BATCH / NB) * C_OUT, 256>>>(x, w, idx, out);
}